// round 1
// baseline (speedup 1.0000x reference)
#include <cuda_runtime.h>
#include <cstdint>
#include <cstddef>

// Problem constants (fixed by the dataset)
#define BB 4
#define NN 512
#define FF 16
#define EE 64

#define ROWS_PER_BLOCK 4
#define THREADS 128

// LeakyReLU(x) = A*x + B*|x|,  A = (1+0.01)/2, B = (1-0.01)/2
#define LR_A 0.505f
#define LR_B 0.495f

// ---------- packed f32x2 helpers ----------
__device__ __forceinline__ unsigned long long pk2(float lo, float hi) {
    unsigned long long d;
    asm("mov.b64 %0, {%1, %2};" : "=l"(d) : "f"(lo), "f"(hi));
    return d;
}
__device__ __forceinline__ void upk2(unsigned long long v, float& lo, float& hi) {
    asm("mov.b64 {%0, %1}, %2;" : "=f"(lo), "=f"(hi) : "l"(v));
}
__device__ __forceinline__ unsigned long long ffma2(unsigned long long a,
                                                    unsigned long long b,
                                                    unsigned long long c) {
    unsigned long long d;
    asm("fma.rn.f32x2 %0, %1, %2, %3;" : "=l"(d) : "l"(a), "l"(b), "l"(c));
    return d;
}

__global__ void __launch_bounds__(THREADS, 3)
edge_embed_kernel(const float* __restrict__ edge,
                  const float* __restrict__ adj,
                  const float* __restrict__ w4,
                  const float* __restrict__ w3,
                  float* __restrict__ out)
{
    // w4 packed as e-pairs: w4p[ep*16+f] = (w4[2ep][f], w4[2ep+1][f])
    __shared__ unsigned long long w4p[32 * 16];          // 4 KB
    __shared__ float w3s[64 * 65];                       // padded, 16.25 KB
    __shared__ float sums[ROWS_PER_BLOCK][EE];           // 1 KB

    const int tid = threadIdx.x;

    for (int idx = tid; idx < 32 * 16; idx += THREADS) {
        int ep = idx >> 4, f = idx & 15;
        w4p[idx] = pk2(w4[(2 * ep) * FF + f], w4[(2 * ep + 1) * FF + f]);
    }
    for (int idx = tid; idx < EE * EE; idx += THREADS) {
        w3s[(idx >> 6) * 65 + (idx & 63)] = w3[idx];
    }
    __syncthreads();

    const int warp = tid >> 5;
    const int lane = tid & 31;
    const int row  = blockIdx.x * ROWS_PER_BLOCK + warp;   // (b*N + i), < 2048

    const float* erow = edge + (size_t)row * (NN * FF);
    const float* arow = adj  + (size_t)row * NN;

    // acc[ep] = (sum_j adj*leaky(x4[.,2ep]), sum_j adj*leaky(x4[.,2ep+1]))
    unsigned long long acc[32];
#pragma unroll
    for (int ep = 0; ep < 32; ++ep) acc[ep] = 0ULL;

    for (int t = 0; t < NN / 32; ++t) {
        const int j = lane + (t << 5);
        const float4* e4 = reinterpret_cast<const float4*>(erow + (size_t)j * FF);
        float4 v0 = e4[0], v1 = e4[1], v2 = e4[2], v3 = e4[3];
        float av = __ldg(arow + j);

        const unsigned long long p2 = pk2(av * LR_A, av * LR_A);
        const unsigned long long q2 = pk2(av * LR_B, av * LR_B);

        unsigned long long bc[16];
        bc[ 0] = pk2(v0.x, v0.x); bc[ 1] = pk2(v0.y, v0.y);
        bc[ 2] = pk2(v0.z, v0.z); bc[ 3] = pk2(v0.w, v0.w);
        bc[ 4] = pk2(v1.x, v1.x); bc[ 5] = pk2(v1.y, v1.y);
        bc[ 6] = pk2(v1.z, v1.z); bc[ 7] = pk2(v1.w, v1.w);
        bc[ 8] = pk2(v2.x, v2.x); bc[ 9] = pk2(v2.y, v2.y);
        bc[10] = pk2(v2.z, v2.z); bc[11] = pk2(v2.w, v2.w);
        bc[12] = pk2(v3.x, v3.x); bc[13] = pk2(v3.y, v3.y);
        bc[14] = pk2(v3.z, v3.z); bc[15] = pk2(v3.w, v3.w);

#pragma unroll 4
        for (int ep = 0; ep < 32; ++ep) {
            const unsigned long long* wrow = &w4p[ep << 4];
            unsigned long long s = 0ULL;
#pragma unroll
            for (int f = 0; f < 16; ++f) {
                s = ffma2(wrow[f], bc[f], s);   // ld.shared.b64 (broadcast) + FFMA2
            }
            unsigned long long ab = s & 0x7FFFFFFF7FFFFFFFULL;  // |s| on both halves
            acc[ep] = ffma2(p2, s,  acc[ep]);
            acc[ep] = ffma2(q2, ab, acc[ep]);
        }
    }

    // Butterfly reduce each e-pair across the 32 lanes (sums over all 512 j)
#pragma unroll
    for (int ep = 0; ep < 32; ++ep) {
        float lo, hi;
        upk2(acc[ep], lo, hi);
#pragma unroll
        for (int off = 16; off; off >>= 1) {
            lo += __shfl_xor_sync(0xFFFFFFFFu, lo, off);
            hi += __shfl_xor_sync(0xFFFFFFFFu, hi, off);
        }
        if (lane == 0) {
            sums[warp][2 * ep]     = lo;
            sums[warp][2 * ep + 1] = hi;
        }
    }
    __syncwarp();

    // theta3: out[row][o] = sum_e sums[e] * w3[o][e]; lane handles o=lane, lane+32
    const float* srow = sums[warp];
    float o0 = 0.0f, o1 = 0.0f;
#pragma unroll
    for (int e = 0; e < EE; ++e) {
        float se = srow[e];                       // uniform address -> broadcast
        o0 = fmaf(se, w3s[lane * 65 + e], o0);    // stride 65 -> conflict-free
        o1 = fmaf(se, w3s[(lane + 32) * 65 + e], o1);
    }
    out[(size_t)row * EE + lane]      = o0;
    out[(size_t)row * EE + 32 + lane] = o1;
}

extern "C" void kernel_launch(void* const* d_in, const int* in_sizes, int n_in,
                              void* d_out, int out_size) {
    const float* edge = (const float*)d_in[0];   // (4,512,512,16) f32
    const float* adj  = (const float*)d_in[1];   // (4,512,512)    f32
    const float* w4   = (const float*)d_in[2];   // (64,16)        f32
    const float* w3   = (const float*)d_in[3];   // (64,64)        f32
    float* out = (float*)d_out;                  // (4,512,64)     f32

    dim3 grid((BB * NN) / ROWS_PER_BLOCK);       // 512 blocks
    edge_embed_kernel<<<grid, THREADS>>>(edge, adj, w4, w3, out);
}

// round 2
// speedup vs baseline: 1.5397x; 1.5397x over previous
#include <cuda_runtime.h>
#include <cstdint>
#include <cstddef>

#define BB 4
#define NN 512
#define FF 16
#define EE 64

#define ROWS_PER_BLOCK 4
#define THREADS 128

// LeakyReLU(x) = A*x + B*|x|
#define LR_A 0.505f
#define LR_B 0.495f

typedef unsigned long long u64;

__device__ __forceinline__ u64 pk2(float lo, float hi) {
    u64 d;
    asm("mov.b64 %0, {%1, %2};" : "=l"(d) : "f"(lo), "f"(hi));
    return d;
}
__device__ __forceinline__ void upk2(u64 v, float& lo, float& hi) {
    asm("mov.b64 {%0, %1}, %2;" : "=f"(lo), "=f"(hi) : "l"(v));
}
__device__ __forceinline__ u64 ffma2(u64 a, u64 b, u64 c) {
    u64 d;
    asm("fma.rn.f32x2 %0, %1, %2, %3;" : "=l"(d) : "l"(a), "l"(b), "l"(c));
    return d;
}

__global__ void __launch_bounds__(THREADS, 2)
edge_embed_kernel(const float* __restrict__ edge,
                  const float* __restrict__ adj,
                  const float* __restrict__ w4,
                  const float* __restrict__ w3,
                  float* __restrict__ out)
{
    // w4 packed as e-pairs, grouped 2-f-wide for LDS.128:
    // w4q[ep][ff] = ( (w4[2ep][2ff],w4[2ep+1][2ff]) , (w4[2ep][2ff+1],w4[2ep+1][2ff+1]) )
    __shared__ ulonglong2 w4q[32][8];                    // 4 KB
    __shared__ float w3s[64 * 65];                       // padded, conflict-free
    __shared__ float sums[ROWS_PER_BLOCK][EE];

    const int tid = threadIdx.x;

    for (int idx = tid; idx < 32 * 8; idx += THREADS) {
        int ep = idx >> 3, ff = idx & 7;
        ulonglong2 v;
        v.x = pk2(w4[(2 * ep) * FF + 2 * ff],     w4[(2 * ep + 1) * FF + 2 * ff]);
        v.y = pk2(w4[(2 * ep) * FF + 2 * ff + 1], w4[(2 * ep + 1) * FF + 2 * ff + 1]);
        w4q[ep][ff] = v;
    }
    for (int idx = tid; idx < EE * EE; idx += THREADS) {
        w3s[(idx >> 6) * 65 + (idx & 63)] = w3[idx];
    }
    __syncthreads();

    const int warp = tid >> 5;
    const int lane = tid & 31;
    const int row  = blockIdx.x * ROWS_PER_BLOCK + warp;   // b*N + i

    const float* erow = edge + (size_t)row * (NN * FF);
    const float* arow = adj  + (size_t)row * NN;

    u64 acc[32];
#pragma unroll
    for (int ep = 0; ep < 32; ++ep) acc[ep] = 0ULL;

    const u64 ABS2 = 0x7FFFFFFF7FFFFFFFULL;

    // Each lane handles two j's per pass: j0 = t*32+lane, j1 = j0+256 (8 passes)
    for (int t = 0; t < 8; ++t) {
        const int j0 = (t << 5) + lane;
        const int j1 = j0 + 256;

        float4 va[4], vb[4];
        const float4* e4a = reinterpret_cast<const float4*>(erow + (size_t)j0 * FF);
        const float4* e4b = reinterpret_cast<const float4*>(erow + (size_t)j1 * FF);
#pragma unroll
        for (int k = 0; k < 4; ++k) { va[k] = e4a[k]; vb[k] = e4b[k]; }

        const float a0 = __ldg(arow + j0);
        const float a1 = __ldg(arow + j1);

        u64 bc0[16], bc1[16];
#pragma unroll
        for (int k = 0; k < 4; ++k) {
            bc0[4 * k + 0] = pk2(va[k].x, va[k].x);
            bc0[4 * k + 1] = pk2(va[k].y, va[k].y);
            bc0[4 * k + 2] = pk2(va[k].z, va[k].z);
            bc0[4 * k + 3] = pk2(va[k].w, va[k].w);
            bc1[4 * k + 0] = pk2(vb[k].x, vb[k].x);
            bc1[4 * k + 1] = pk2(vb[k].y, vb[k].y);
            bc1[4 * k + 2] = pk2(vb[k].z, vb[k].z);
            bc1[4 * k + 3] = pk2(vb[k].w, vb[k].w);
        }

        const u64 p0 = pk2(a0 * LR_A, a0 * LR_A);
        const u64 q0 = pk2(a0 * LR_B, a0 * LR_B);
        const u64 p1 = pk2(a1 * LR_A, a1 * LR_A);
        const u64 q1 = pk2(a1 * LR_B, a1 * LR_B);

#pragma unroll 4
        for (int ep = 0; ep < 32; ++ep) {
            u64 s0 = 0ULL, s1 = 0ULL;
#pragma unroll
            for (int ff = 0; ff < 8; ++ff) {
                ulonglong2 w2 = w4q[ep][ff];          // LDS.128, broadcast
                s0 = ffma2(w2.x, bc0[2 * ff],     s0);
                s1 = ffma2(w2.x, bc1[2 * ff],     s1);
                s0 = ffma2(w2.y, bc0[2 * ff + 1], s0);
                s1 = ffma2(w2.y, bc1[2 * ff + 1], s1);
            }
            acc[ep] = ffma2(p0, s0,        acc[ep]);
            acc[ep] = ffma2(q0, s0 & ABS2, acc[ep]);
            acc[ep] = ffma2(p1, s1,        acc[ep]);
            acc[ep] = ffma2(q1, s1 & ABS2, acc[ep]);
        }
    }

    // Butterfly reduce each e-pair across lanes
#pragma unroll
    for (int ep = 0; ep < 32; ++ep) {
        float lo, hi;
        upk2(acc[ep], lo, hi);
#pragma unroll
        for (int off = 16; off; off >>= 1) {
            lo += __shfl_xor_sync(0xFFFFFFFFu, lo, off);
            hi += __shfl_xor_sync(0xFFFFFFFFu, hi, off);
        }
        if (lane == 0) {
            sums[warp][2 * ep]     = lo;
            sums[warp][2 * ep + 1] = hi;
        }
    }
    __syncwarp();

    // theta3: out[row][o] = sum_e sums[e] * w3[o][e]
    const float* srow = sums[warp];
    float o0 = 0.0f, o1 = 0.0f;
#pragma unroll
    for (int e = 0; e < EE; ++e) {
        float se = srow[e];
        o0 = fmaf(se, w3s[lane * 65 + e], o0);
        o1 = fmaf(se, w3s[(lane + 32) * 65 + e], o1);
    }
    out[(size_t)row * EE + lane]      = o0;
    out[(size_t)row * EE + 32 + lane] = o1;
}

extern "C" void kernel_launch(void* const* d_in, const int* in_sizes, int n_in,
                              void* d_out, int out_size) {
    const float* edge = (const float*)d_in[0];   // (4,512,512,16) f32
    const float* adj  = (const float*)d_in[1];   // (4,512,512)    f32
    const float* w4   = (const float*)d_in[2];   // (64,16)        f32
    const float* w3   = (const float*)d_in[3];   // (64,64)        f32
    float* out = (float*)d_out;                  // (4,512,64)     f32

    dim3 grid((BB * NN) / ROWS_PER_BLOCK);       // 512 blocks
    edge_embed_kernel<<<grid, THREADS>>>(edge, adj, w4, w3, out);
}